// round 3
// baseline (speedup 1.0000x reference)
#include <cuda_runtime.h>
#include <math.h>

#define NMAX 10000
#define EMAX 320000

// ---------------- scratch (device globals; no allocation allowed) -------------
__device__ int   g_is64;
__device__ float g_deg[NMAX];
__device__ float g_dis[NMAX];
__device__ int   g_cnt[NMAX];
__device__ int   g_rowptr[NMAX + 1];
__device__ int   g_srcd[EMAX];
__device__ int   g_dstd[EMAX];
__device__ int   g_col[EMAX];
__device__ float g_cnorm[EMAX];
__device__ __align__(256) float g_h[NMAX * 64];
__device__ __align__(256) float g_acc[NMAX * 64];
__device__ __align__(256) float g_B0[NMAX * 64];
__device__ __align__(256) float g_B1[NMAX * 64];
__device__ __align__(256) float g_B2[NMAX * 64];

constexpr int TPB = 256;
constexpr int NPB = 8;   // nodes per block (one per warp)

// ---------------- preprocessing ----------------------------------------------
__global__ void zero_k(int n) {
    int i = blockIdx.x * blockDim.x + threadIdx.x;
    if (i < n) {
        g_deg[i] = 0.f;
        g_cnt[i] = 0;
    }
}

// Detect whether edge_index is stored as int64 or int32.
// If int64 (indices < 2^31, nonnegative), every odd 32-bit word is 0.
__global__ void detect_k(const int* __restrict__ ei32, int nwords) {
    __shared__ int bad;
    if (threadIdx.x == 0) bad = 0;
    __syncthreads();
    int nsamp = nwords / 2;
    if (nsamp > 4096) nsamp = 4096;
    for (int i = threadIdx.x; i < nsamp; i += blockDim.x)
        if (ei32[2 * i + 1] != 0) bad = 1;
    __syncthreads();
    if (threadIdx.x == 0) g_is64 = (bad == 0) ? 1 : 0;
}

__global__ void prep_edges_k(const void* __restrict__ ei,
                             const float* __restrict__ w, int E, int n) {
    int e = blockIdx.x * blockDim.x + threadIdx.x;
    if (e >= E) return;
    int s, d;
    if (g_is64) {
        const long long* p = (const long long*)ei;
        s = (int)p[e];
        d = (int)p[(long long)E + e];
    } else {
        const int* p = (const int*)ei;
        s = p[e];
        d = p[E + e];
    }
    // defensive clamp: wrong values give wrong output (rel_err), not a crash
    s = (s < 0) ? 0 : ((s >= n) ? n - 1 : s);
    d = (d < 0) ? 0 : ((d >= n) ? n - 1 : d);
    g_srcd[e] = s;
    g_dstd[e] = d;
    atomicAdd(&g_deg[s], w[e]);
    atomicAdd(&g_cnt[d], 1);
}

__global__ void dis_k(int n) {
    int i = blockIdx.x * blockDim.x + threadIdx.x;
    if (i < n) {
        float d = g_deg[i];
        g_dis[i] = (d > 0.f) ? (1.f / sqrtf(d)) : 0.f;
    }
}

// single-block exclusive scan of g_cnt -> g_rowptr; g_cnt becomes the cursor
__global__ void scan_k(int n) {
    __shared__ int ssum[1024];
    int t = threadIdx.x;
    int chunk = (n + 1023) / 1024;
    int beg = t * chunk;
    int end = beg + chunk;
    if (beg > n) beg = n;
    if (end > n) end = n;
    int s = 0;
    for (int i = beg; i < end; i++) s += g_cnt[i];
    ssum[t] = s;
    __syncthreads();
    for (int off = 1; off < 1024; off <<= 1) {
        int v = (t >= off) ? ssum[t - off] : 0;
        __syncthreads();
        ssum[t] += v;
        __syncthreads();
    }
    int run = (t == 0) ? 0 : ssum[t - 1];
    for (int i = beg; i < end; i++) {
        int c = g_cnt[i];
        g_rowptr[i] = run;
        g_cnt[i] = run;   // cursor for scatter
        run += c;
    }
    if (t == 1023) g_rowptr[n] = ssum[1023];
}

__global__ void scatter_k(const float* __restrict__ w, int E) {
    int e = blockIdx.x * blockDim.x + threadIdx.x;
    if (e >= E) return;
    int s = g_srcd[e], d = g_dstd[e];
    float nv = -g_dis[s] * w[e] * g_dis[d];
    int p = atomicAdd(&g_cnt[d], 1);
    g_col[p]   = s;
    g_cnorm[p] = nv;
}

// ---------------- fused Cheb step: SpMM (CSR by dst) + out += T_k @ W_k ------
// MODE 0: no propagate; T = Tin row; acc = T @ W + bias   (k == 0)
// MODE 1: T = propagate(Tin); Tnext = T; acc += T @ W     (k == 1)
// MODE 2: T = 2*propagate(Tin) - Tprev; Tnext = T; acc += T @ W  (k >= 2)
template <int IN, int OUT, int MODE>
__global__ __launch_bounds__(TPB)
void cheb_step(const float* __restrict__ Tin,
               const float* __restrict__ Tprev,
               float* __restrict__ Tnext,
               float* __restrict__ acc,
               const float* __restrict__ W,
               const float* __restrict__ bias,
               int n) {
    __shared__ float Ts[NPB][IN + 1];
    __shared__ float Ws[IN * OUT];

    int tid  = threadIdx.x;
    int wrp  = tid >> 5;
    int lane = tid & 31;
    int nd   = blockIdx.x * NPB + wrp;

    // stage W_k into smem
    for (int i = tid; i < IN * OUT; i += TPB) Ws[i] = W[i];

    if (nd < n) {
        if (MODE == 0) {
            for (int f = lane; f < IN; f += 32) Ts[wrp][f] = Tin[nd * IN + f];
        } else if (IN <= 8) {
            // narrow features: edge-parallel across the warp (32/IN edges/iter)
            int beg = g_rowptr[nd], end = g_rowptr[nd + 1];
            int feat = lane & (IN - 1);
            int eo   = lane / IN;
            float s = 0.f;
            for (int e = beg + eo; e < end; e += 32 / IN)
                s += g_cnorm[e] * __ldg(&Tin[g_col[e] * IN + feat]);
            for (int off = 16; off >= IN; off >>= 1)
                s += __shfl_xor_sync(0xffffffffu, s, off);
            if (lane < IN) {
                float t = (MODE == 2) ? 2.f * s - Tprev[nd * IN + lane] : s;
                Tnext[nd * IN + lane] = t;
                Ts[wrp][lane] = t;
            }
        } else {
            // wide features: lane-per-feature, full 256B row gathers
            int beg = g_rowptr[nd], end = g_rowptr[nd + 1];
            int f0 = lane, f1 = lane + 32;
            float s0 = 0.f, s1 = 0.f;
            for (int e = beg; e < end; e++) {
                float nv = g_cnorm[e];
                const float* p = Tin + g_col[e] * IN;
                s0 += nv * __ldg(&p[f0]);
                if (IN > 32 && f1 < IN) s1 += nv * __ldg(&p[f1]);
            }
            {
                float t0 = (MODE == 2) ? 2.f * s0 - Tprev[nd * IN + f0] : s0;
                Tnext[nd * IN + f0] = t0;
                Ts[wrp][f0] = t0;
            }
            if (IN > 32 && f1 < IN) {
                float t1 = (MODE == 2) ? 2.f * s1 - Tprev[nd * IN + f1] : s1;
                Tnext[nd * IN + f1] = t1;
                Ts[wrp][f1] = t1;
            }
        }
    }
    __syncthreads();

    // block GEMM: acc[node, j] (+)= sum_i Ts[node][i] * Ws[i][j]
    constexpr int JS     = (OUT > 32) ? 64 : 32;
    constexpr int GROUPS = TPB / JS;
    constexpr int NPG    = NPB / GROUPS;
    int j = tid % JS;
    int g = tid / JS;
    if (j < OUT) {
        float a[NPG];
#pragma unroll
        for (int q = 0; q < NPG; q++) a[q] = 0.f;
#pragma unroll 4
        for (int i = 0; i < IN; i++) {
            float wv = Ws[i * OUT + j];
#pragma unroll
            for (int q = 0; q < NPG; q++) a[q] += wv * Ts[g * NPG + q][i];
        }
#pragma unroll
        for (int q = 0; q < NPG; q++) {
            int node = blockIdx.x * NPB + g * NPG + q;
            if (node < n) {
                if (MODE == 0)
                    acc[node * OUT + j] = a[q] + bias[j];
                else
                    acc[node * OUT + j] += a[q];
            }
        }
    }
}

// ---------------- epilogues --------------------------------------------------
__global__ void silu_k(const float* __restrict__ a, float* __restrict__ h, int cnt) {
    int i = blockIdx.x * blockDim.x + threadIdx.x;
    if (i < cnt) {
        float v = a[i];
        h[i] = v / (1.f + expf(-v));
    }
}

__global__ void final_k(const float* __restrict__ h, const float* __restrict__ W4,
                        float* __restrict__ out, int n) {
    int i = blockIdx.x * blockDim.x + threadIdx.x;
    if (i < n) {
        float s = 0.f;
#pragma unroll
        for (int k = 0; k < 30; k++) s += h[i * 30 + k] * W4[k];
        out[i] = 1.f / (1.f + expf(-s));
    }
}

// ---------------- host orchestration -----------------------------------------
template <int IN, int OUT>
static void run_layer(const float* hin, const float* W, const float* bias, int K,
                      float* acc, float* B0, float* B1, float* B2, int n) {
    int blocks = (n + NPB - 1) / NPB;
    cheb_step<IN, OUT, 0><<<blocks, TPB>>>(hin, nullptr, nullptr, acc, W, bias, n);
    if (K > 1) {
        cheb_step<IN, OUT, 1><<<blocks, TPB>>>(hin, nullptr, B1, acc, W + IN * OUT,
                                               nullptr, n);
        const float* tx0 = hin;
        float* tx1 = B1;
        float* nxt = B2;
        float* spare = B0;
        for (int k = 2; k < K; k++) {
            cheb_step<IN, OUT, 2><<<blocks, TPB>>>(tx1, tx0, nxt, acc,
                                                   W + k * IN * OUT, nullptr, n);
            float* old_nxt = nxt;
            float* next_nxt = (k == 2) ? spare : (float*)tx0;
            tx0 = tx1;
            tx1 = old_nxt;
            nxt = next_nxt;
        }
    }
}

extern "C" void kernel_launch(void* const* d_in, const int* in_sizes, int n_in,
                              void* d_out, int out_size) {
    const float* x  = (const float*)d_in[0];
    const void*  ei = d_in[1];
    const float* ew = (const float*)d_in[2];
    const float* W1 = (const float*)d_in[3];
    const float* b1 = (const float*)d_in[4];
    const float* W2 = (const float*)d_in[5];
    const float* b2 = (const float*)d_in[6];
    const float* W3 = (const float*)d_in[7];
    const float* b3 = (const float*)d_in[8];
    const float* W4 = (const float*)d_in[9];
    float* out = (float*)d_out;

    int n = in_sizes[0] / 4;   // 10000
    int E = in_sizes[2];       // 320000

    float *p_h, *p_acc, *p_B0, *p_B1, *p_B2;
    cudaGetSymbolAddress((void**)&p_h,   g_h);
    cudaGetSymbolAddress((void**)&p_acc, g_acc);
    cudaGetSymbolAddress((void**)&p_B0,  g_B0);
    cudaGetSymbolAddress((void**)&p_B1,  g_B1);
    cudaGetSymbolAddress((void**)&p_B2,  g_B2);

    // preprocessing: degrees + CSR by dst
    int eb = (E + TPB - 1) / TPB;
    zero_k<<<(n + TPB - 1) / TPB, TPB>>>(n);
    detect_k<<<1, 256>>>((const int*)ei, 2 * E);
    prep_edges_k<<<eb, TPB>>>(ei, ew, E, n);
    dis_k<<<(n + TPB - 1) / TPB, TPB>>>(n);
    scan_k<<<1, 1024>>>(n);
    scatter_k<<<eb, TPB>>>(ew, E);

    // layer 1: ChebConv(4 -> 64, K=120) + SiLU
    run_layer<4, 64>(x, W1, b1, 120, p_acc, p_B0, p_B1, p_B2, n);
    silu_k<<<(n * 64 + TPB - 1) / TPB, TPB>>>(p_acc, p_h, n * 64);

    // layer 2: ChebConv(64 -> 60, K=120) + SiLU
    run_layer<64, 60>(p_h, W2, b2, 120, p_acc, p_B0, p_B1, p_B2, n);
    silu_k<<<(n * 60 + TPB - 1) / TPB, TPB>>>(p_acc, p_h, n * 60);

    // layer 3: ChebConv(60 -> 30, K=20) + SiLU
    run_layer<60, 30>(p_h, W3, b3, 20, p_acc, p_B0, p_B1, p_B2, n);
    silu_k<<<(n * 30 + TPB - 1) / TPB, TPB>>>(p_acc, p_h, n * 30);

    // layer 4: ChebConv(30 -> 1, K=1) + sigmoid
    final_k<<<(n + TPB - 1) / TPB, TPB>>>(p_h, W4, out, n);
}